// round 11
// baseline (speedup 1.0000x reference)
#include <cuda_runtime.h>
#include <cstdint>

// out[b,t,:] = ((vf[b] @ Wv + bv) @ Wp + bp), broadcast over t.
// (keys/values broadcast over T -> softmax uniform -> y == v; x/Wq/Wk drop out)
//
// Single fused persistent kernel, 128 blocks x 512 threads:
//   work item = (slab of 128 cols, k-chunk of 64 rows): 8 x 16 = 128 blocks.
//   Phase A: g_p1[kc][b][c] = sum_{k in chunk} vf[b,k] * Wv[k,c]
//   [prefetch Wp tile into regs]  barrier0 (release/acquire, no full fences)
//   Phase B: stage vv = fold16(g_p1)+bv, then g_p2 = vv-chunk @ Wp (prefetched)
//   [prefetch bp]                 barrier1
//   Phase C: r = fold16(g_p2)+bp; broadcast 32 rows via TMA bulk (32 lanes)
// All float reductions fixed-order (deterministic).

#define C_     1024
#define B_     4
#define T_     1024
#define GRID_  128
#define BLOCK_ 512
#define NKC_   16     // k-chunks
#define KCH_   64     // rows per k-chunk
#define NSLAB_ 8      // column slabs
#define SLABW_ 128    // columns per slab

__device__ float g_p1[NKC_][B_][C_];   // 256 KB, L2-resident
__device__ float g_p2[NKC_][B_][C_];   // 256 KB
__device__ unsigned g_barcnt[2];       // monotonic across graph replays

// Grid barrier: atom.release orders this block's prior global stores;
// ld.acquire orders subsequent reads of other blocks' partials.
// Monotonic counter -> replay/wrap safe.
__device__ __forceinline__ void grid_barrier(int i) {
    __syncthreads();
    if (threadIdx.x == 0) {
        unsigned* ctr = &g_barcnt[i];
        unsigned old;
        asm volatile("atom.release.gpu.global.add.u32 %0, [%1], 1;"
                     : "=r"(old) : "l"(ctr) : "memory");
        const unsigned target = (old / GRID_ + 1u) * GRID_;
        unsigned cur;
        do {
            asm volatile("ld.acquire.gpu.global.u32 %0, [%1];"
                         : "=r"(cur) : "l"(ctr) : "memory");
        } while ((int)(cur - target) < 0);
    }
    __syncthreads();
}

struct WTile { float4 w0, w1, w2, w3; };

// Load this thread's 4-row x float4 tile of W (4 independent LDG.128).
__device__ __forceinline__ WTile load_wtile(const float* __restrict__ W,
                                            int k0, int slab, int tid) {
    const int lane = tid & 31;
    const int w    = tid >> 5;
    const float* wp = &W[(size_t)(k0 + w * 4) * C_ + slab * SLABW_ + lane * 4];
    WTile t;
    t.w0 = *(const float4*)(wp);
    t.w1 = *(const float4*)(wp + C_);
    t.w2 = *(const float4*)(wp + 2 * C_);
    t.w3 = *(const float4*)(wp + 3 * C_);
    return t;
}

// Rank-4 update with preloaded W tile + fixed-order in-block k reduce.
__device__ __forceinline__ void gemv_compute(
    const WTile& t,
    const float (&s_in)[B_][KCH_],
    float (&s_red)[16][B_][SLABW_],
    int slab, int tid,
    float* __restrict__ gout)          // g_pX[kc] : [B_][C_] flat
{
    const int lane = tid & 31;
    const int w    = tid >> 5;
    const int kw   = w * 4;

#pragma unroll
    for (int b = 0; b < B_; b++) {
        const float a0 = s_in[b][kw + 0];
        const float a1 = s_in[b][kw + 1];
        const float a2 = s_in[b][kw + 2];
        const float a3 = s_in[b][kw + 3];
        float4 acc;
        acc.x = a0 * t.w0.x + a1 * t.w1.x + a2 * t.w2.x + a3 * t.w3.x;
        acc.y = a0 * t.w0.y + a1 * t.w1.y + a2 * t.w2.y + a3 * t.w3.y;
        acc.z = a0 * t.w0.z + a1 * t.w1.z + a2 * t.w2.z + a3 * t.w3.z;
        acc.w = a0 * t.w0.w + a1 * t.w1.w + a2 * t.w2.w + a3 * t.w3.w;
        *(float4*)&s_red[w][b][lane * 4] = acc;
    }
    __syncthreads();

    const int rb = tid >> 7;
    const int rc = tid & 127;
    float s = 0.f;
#pragma unroll
    for (int ww = 0; ww < 16; ww++) s += s_red[ww][rb][rc];
    gout[rb * C_ + slab * SLABW_ + rc] = s;
}

__global__ void __launch_bounds__(BLOCK_, 1) ca_fused(
    const float* __restrict__ vf, const float* __restrict__ Wv,
    const float* __restrict__ bv, const float* __restrict__ Wp,
    const float* __restrict__ bp, float* __restrict__ out)
{
    __shared__ __align__(16) float s_in[B_][KCH_];            // 1 KB
    __shared__ __align__(16) float s_red[16][B_][SLABW_];     // 32 KB
    __shared__ __align__(16) float s_row[C_];                 // 4 KB

    const int bid  = blockIdx.x;
    const int tid  = threadIdx.x;
    const int slab = bid & (NSLAB_ - 1);
    const int kc   = bid >> 3;
    const int k0   = kc * KCH_;

    // ---- Phase A: g_p1[kc] = vf-chunk @ Wv-tile ----
    const WTile tv = load_wtile(Wv, k0, slab, tid);
    if (tid < B_ * KCH_) {
        const int b = tid >> 6, j = tid & 63;
        s_in[b][j] = vf[b * C_ + k0 + j];
    }
    __syncthreads();
    gemv_compute(tv, s_in, s_red, slab, tid, &g_p1[kc][0][0]);

    // Prefetch Wp tile BEFORE the barrier: hides its DRAM latency behind the wait.
    const WTile tp = load_wtile(Wp, k0, slab, tid);
    grid_barrier(0);

    // ---- Phase B: stage vv chunk (fold 16 partials + bv), then @ Wp-tile ----
    __syncthreads();   // protect s_in reuse vs. phase A readers
    if (tid < B_ * KCH_) {
        const int b = tid >> 6, j = tid & 63;
        const int K = k0 + j;
        float s = bv[K];
#pragma unroll
        for (int p = 0; p < NKC_; p++) s += g_p1[p][b][K];
        s_in[b][j] = s;
    }
    __syncthreads();
    gemv_compute(tp, s_in, s_red, slab, tid, &g_p2[kc][0][0]);

    // Prefetch bp before the barrier.
    const int b  = bid >> 5;
    const int t0 = (bid & 31) * 32;
    float4 r = make_float4(0.f, 0.f, 0.f, 0.f);
    if (tid < 256) r = *(const float4*)&bp[tid * 4];
    grid_barrier(1);

    // ---- Phase C: r[b] = fold 16 partials + bp; TMA-broadcast 32 rows ----
    if (tid < 256) {
        const int c4 = tid * 4;
#pragma unroll
        for (int p = 0; p < NKC_; p++) {
            const float4 v = *(const float4*)&g_p2[p][b][c4];
            r.x += v.x; r.y += v.y; r.z += v.z; r.w += v.w;
        }
        *(float4*)&s_row[c4] = r;
    }
    __syncthreads();

    if (tid < 32) {
        asm volatile("fence.proxy.async.shared::cta;" ::: "memory");
        const uint32_t saddr = (uint32_t)__cvta_generic_to_shared(s_row);
        const float* dst = &out[(size_t)(b * T_ + t0 + tid) * C_];
        asm volatile(
            "cp.async.bulk.global.shared::cta.bulk_group [%0], [%1], %2;"
            :: "l"(dst), "r"(saddr), "r"(4096) : "memory");
        asm volatile("cp.async.bulk.commit_group;" ::: "memory");
        asm volatile("cp.async.bulk.wait_group 0;" ::: "memory");
    }
}

// Inputs: 0 x, 1 vf, 2 Wq, 3 bq, 4 Wk, 5 bk, 6 Wv, 7 bv, 8 Wp, 9 bp
extern "C" void kernel_launch(void* const* d_in, const int* in_sizes, int n_in,
                              void* d_out, int out_size) {
    const float* vf = (const float*)d_in[1];
    const float* Wv = (const float*)d_in[6];
    const float* bv = (const float*)d_in[7];
    const float* Wp = (const float*)d_in[8];
    const float* bp = (const float*)d_in[9];
    float* out = (float*)d_out;

    ca_fused<<<GRID_, BLOCK_>>>(vf, Wv, bv, Wp, bp, out);
}